// round 6
// baseline (speedup 1.0000x reference)
#include <cuda_runtime.h>
#include <math.h>

#define RR       2336
#define CIN      4
#define COUT     16
#define NK       2
#define NTHREADS 448
#define NWARP    14
#define RT       112          // route-threads per block (tid >> 2)
#define RPTF     20           // full j iterations (20*112 = 2240)
#define RPT      21
#define TAILRT   96           // 2336 - 2240 routes in tail (warps 12,13... rt<96)

typedef unsigned long long u64;

// W repacked: [k][og*4+i][r] float4 (value covers outputs o = og*4 .. og*4+3, input i)
__device__ float4 g_Wt4[NK * 16 * RR];

__global__ void wtrans_kernel(const float* __restrict__ W) {
    int t = blockIdx.x * blockDim.x + threadIdx.x;
    if (t >= NK * 16 * RR) return;
    int r  = t % RR;
    int q  = t / RR;          // k*16 + og*4 + i
    int i  = q & 3;
    int og = (q >> 2) & 3;
    int k  = q >> 4;
    const float4* src = (const float4*)W;   // [(k,r,i)][og]
    g_Wt4[t] = src[((k * RR + r) * CIN + i) * 4 + og];
}

// ---------------- packed f32x2 helpers ----------------
__device__ __forceinline__ u64 fma2(u64 a, u64 b, u64 c) {
    u64 d; asm("fma.rn.f32x2 %0, %1, %2, %3;" : "=l"(d) : "l"(a), "l"(b), "l"(c)); return d;
}
__device__ __forceinline__ u64 add2(u64 a, u64 b) {
    u64 d; asm("add.rn.f32x2 %0, %1, %2;" : "=l"(d) : "l"(a), "l"(b)); return d;
}
__device__ __forceinline__ u64 mul2(u64 a, u64 b) {
    u64 d; asm("mul.rn.f32x2 %0, %1, %2;" : "=l"(d) : "l"(a), "l"(b)); return d;
}
__device__ __forceinline__ u64 pack2(float x, float y) {
    u64 d; asm("mov.b64 %0, {%1, %2};" : "=l"(d) : "f"(x), "f"(y)); return d;
}
__device__ __forceinline__ float2 unpack2(u64 d) {
    float x, y; asm("mov.b64 {%0, %1}, %2;" : "=f"(x), "=f"(y) : "l"(d));
    return make_float2(x, y);
}
__device__ __forceinline__ u64 bcast2(float x) { return pack2(x, x); }

// ---- block reduction over the rt dimension; og-lanes kept separate ----
// lanes 4k+og all end with the og-specific totals.
template <int C>
__device__ __forceinline__ void reduce_rt(float* v, float* red, int lane, int wid, int og) {
#pragma unroll
    for (int c = 0; c < C; ++c) {
        float x = v[c];
        x += __shfl_xor_sync(0xffffffffu, x, 4);
        x += __shfl_xor_sync(0xffffffffu, x, 8);
        x += __shfl_xor_sync(0xffffffffu, x, 16);
        v[c] = x;
    }
    __syncthreads();
    if (lane < 4) {
#pragma unroll
        for (int c = 0; c < C; ++c) red[(wid * 4 + lane) * C + c] = v[c];
    }
    __syncthreads();
#pragma unroll
    for (int c = 0; c < C; ++c) {
        float t = 0.f;
#pragma unroll
        for (int w = 0; w < NWARP; ++w) t += red[(w * 4 + og) * C + c];
        v[c] = t;
    }
}

// squash on this thread's 4 components; norm completed across og-lanes via shfl
__device__ __forceinline__ void squash4(const float* s, float* v) {
    float n = fmaf(s[0], s[0], fmaf(s[1], s[1], fmaf(s[2], s[2], s[3] * s[3])));
    n += __shfl_xor_sync(0xffffffffu, n, 1);
    n += __shfl_xor_sync(0xffffffffu, n, 2);
    float f = sqrtf(n) / (1.f + n);
#pragma unroll
    for (int o = 0; o < 4; ++o) v[o] = s[o] * f;
}

__device__ __forceinline__ float norm16_of4(const float* v) {
    float n = fmaf(v[0], v[0], fmaf(v[1], v[1], fmaf(v[2], v[2], v[3] * v[3])));
    n += __shfl_xor_sync(0xffffffffu, n, 1);
    n += __shfl_xor_sync(0xffffffffu, n, 2);
    return sqrtf(n);
}

// one block handles batches (2*bid, 2*bid+1)
__global__ __launch_bounds__(NTHREADS, 1)
void caps_kernel(const float* __restrict__ u, float* __restrict__ out) {
    extern __shared__ float sm[];
    ulonglong2* ujiS = (ulonglong2*)sm;       // batch1 u_ji: slot r*4+og (16B)
    float*      red  = sm + RR * 16;

    const int tid  = threadIdx.x;
    const int lane = tid & 31;
    const int wid  = tid >> 5;
    const int og   = tid & 3;                 // output group: o = og*4 .. og*4+3
    const int rt   = tid >> 2;                // route-thread 0..111
    const bool tailok = (rt < TAILRT);        // warp-uniform (warps 12,13 excluded)

    const int b0 = blockIdx.x * 2;
    const int b1 = b0 + 1;
    const float4* u0p = (const float4*)(u + (size_t)b0 * RR * CIN);
    const float4* u1p = (const float4*)(u + (size_t)b1 * RR * CIN);

    float cls0[NK], cls1[NK];

    for (int k = 0; k < NK; ++k) {
        // base pointer for input i=0 of this og; input i at offset i*RR
        const ulonglong2* WtP =
            (const ulonglong2*)(g_Wt4 + (k * 16 + og * 4) * RR);

        // ===== Phase A: stream W once; b0 uji -> regs, b1 uji -> smem;
        //       init route-sums folded in. =====
        u64 uji0p[RPT][2];
        u64 ss0[2] = {0ull, 0ull}, ss1[2] = {0ull, 0ull};

#define ROUTE_A(JIDX, RVAL)                                                    \
        {                                                                      \
            const int r_ = (RVAL);                                             \
            float4 a0 = u0p[r_];                                               \
            float4 a1 = u1p[r_];                                               \
            ulonglong2 w0 = WtP[r_];                                           \
            ulonglong2 w1 = WtP[RR + r_];                                      \
            ulonglong2 w2 = WtP[2 * RR + r_];                                  \
            ulonglong2 w3 = WtP[3 * RR + r_];                                  \
            u64 e0 = fma2(bcast2(a0.x), w0.x, fma2(bcast2(a0.y), w1.x,        \
                     fma2(bcast2(a0.z), w2.x, mul2(bcast2(a0.w), w3.x))));     \
            u64 e1 = fma2(bcast2(a0.x), w0.y, fma2(bcast2(a0.y), w1.y,        \
                     fma2(bcast2(a0.z), w2.y, mul2(bcast2(a0.w), w3.y))));     \
            uji0p[JIDX][0] = e0; uji0p[JIDX][1] = e1;                          \
            ss0[0] = add2(ss0[0], e0); ss0[1] = add2(ss0[1], e1);              \
            u64 q0 = fma2(bcast2(a1.x), w0.x, fma2(bcast2(a1.y), w1.x,        \
                     fma2(bcast2(a1.z), w2.x, mul2(bcast2(a1.w), w3.x))));     \
            u64 q1 = fma2(bcast2(a1.x), w0.y, fma2(bcast2(a1.y), w1.y,        \
                     fma2(bcast2(a1.z), w2.y, mul2(bcast2(a1.w), w3.y))));     \
            ss1[0] = add2(ss1[0], q0); ss1[1] = add2(ss1[1], q1);              \
            ulonglong2 qq; qq.x = q0; qq.y = q1;                               \
            ujiS[r_ * 4 + og] = qq;                                            \
        }

#pragma unroll
        for (int j = 0; j < RPTF; ++j)
            ROUTE_A(j, rt + j * RT)
        if (tailok) {
            ROUTE_A(RPTF, rt + RPTF * RT)
        } else {
            uji0p[RPTF][0] = 0ull; uji0p[RPTF][1] = 0ull;
        }

        // ===== merged init reduction + squash for both batches =====
        float v0[4], v1[4];
        {
            float sb[8];
            float2 t;
            t = unpack2(ss0[0]); sb[0] = t.x; sb[1] = t.y;
            t = unpack2(ss0[1]); sb[2] = t.x; sb[3] = t.y;
            t = unpack2(ss1[0]); sb[4] = t.x; sb[5] = t.y;
            t = unpack2(ss1[1]); sb[6] = t.x; sb[7] = t.y;
            reduce_rt<8>(sb, red, lane, wid, og);
#pragma unroll
            for (int c = 0; c < 8; ++c) sb[c] *= (1.f / RR);
            squash4(sb, v0);
            squash4(sb + 4, v1);
        }

        // ===== Routing: batch 0 (register u_ji) =====
        {
            u64 vp[2] = {pack2(v0[0], v0[1]), pack2(v0[2], v0[3])};
            float blr[RPT];
            for (int it = 0; it < 2; ++it) {
                float accw = 0.f;
                u64 acc0 = 0ull, acc1 = 0ull;

#define SWEEP0(JIDX)                                                           \
                {                                                              \
                    u64 dp = fma2(uji0p[JIDX][1], vp[1],                       \
                                  mul2(uji0p[JIDX][0], vp[0]));                \
                    float2 dd = unpack2(dp);                                   \
                    float d = dd.x + dd.y;                                     \
                    d += __shfl_xor_sync(0xffffffffu, d, 1);                   \
                    d += __shfl_xor_sync(0xffffffffu, d, 2);                   \
                    float nb = (it == 0) ? d : (blr[JIDX] + d);                \
                    blr[JIDX] = nb;                                            \
                    float w = __expf(nb);                                      \
                    accw += w;                                                 \
                    u64 wp = bcast2(w);                                        \
                    acc0 = fma2(wp, uji0p[JIDX][0], acc0);                     \
                    acc1 = fma2(wp, uji0p[JIDX][1], acc1);                     \
                }

#pragma unroll
                for (int j = 0; j < RPTF; ++j)
                    SWEEP0(j)
                if (tailok)
                    SWEEP0(RPTF)

                float av[5];
                float2 t0 = unpack2(acc0), t1 = unpack2(acc1);
                av[0] = t0.x; av[1] = t0.y; av[2] = t1.x; av[3] = t1.y;
                av[4] = accw;
                reduce_rt<5>(av, red, lane, wid, og);
                float invZ = 1.f / av[4];
                float s4[4];
#pragma unroll
                for (int o = 0; o < 4; ++o) s4[o] = av[o] * invZ;
                squash4(s4, v0);
                vp[0] = pack2(v0[0], v0[1]); vp[1] = pack2(v0[2], v0[3]);
            }
            cls0[k] = norm16_of4(v0);
        }

        // ===== Routing: batch 1 (smem u_ji, thread-private slots) =====
        {
            u64 vp[2] = {pack2(v1[0], v1[1]), pack2(v1[2], v1[3])};
            float blr[RPT];
            for (int it = 0; it < 2; ++it) {
                float accw = 0.f;
                u64 acc0 = 0ull, acc1 = 0ull;

#define SWEEP1(JIDX, RVAL)                                                     \
                {                                                              \
                    const int r_ = (RVAL);                                     \
                    ulonglong2 qt = ujiS[r_ * 4 + og];                         \
                    u64 dp = fma2(qt.y, vp[1], mul2(qt.x, vp[0]));             \
                    float2 dd = unpack2(dp);                                   \
                    float d = dd.x + dd.y;                                     \
                    d += __shfl_xor_sync(0xffffffffu, d, 1);                   \
                    d += __shfl_xor_sync(0xffffffffu, d, 2);                   \
                    float nb = (it == 0) ? d : (blr[JIDX] + d);                \
                    blr[JIDX] = nb;                                            \
                    float w = __expf(nb);                                      \
                    accw += w;                                                 \
                    u64 wp = bcast2(w);                                        \
                    acc0 = fma2(wp, qt.x, acc0);                               \
                    acc1 = fma2(wp, qt.y, acc1);                               \
                }

#pragma unroll
                for (int j = 0; j < RPTF; ++j)
                    SWEEP1(j, rt + j * RT)
                if (tailok)
                    SWEEP1(RPTF, rt + RPTF * RT)

                float av[5];
                float2 t0 = unpack2(acc0), t1 = unpack2(acc1);
                av[0] = t0.x; av[1] = t0.y; av[2] = t1.x; av[3] = t1.y;
                av[4] = accw;
                reduce_rt<5>(av, red, lane, wid, og);
                float invZ = 1.f / av[4];
                float s4[4];
#pragma unroll
                for (int o = 0; o < 4; ++o) s4[o] = av[o] * invZ;
                squash4(s4, v1);
                vp[0] = pack2(v1[0], v1[1]); vp[1] = pack2(v1[2], v1[3]);
            }
            cls1[k] = norm16_of4(v1);
        }
        // ujiS slots are thread-private; reduce_rt barriers order the k loop
    }

    // ---------------- final 2-way softmax per batch
    if (tid == 0) {
        float m0 = fmaxf(cls0[0], cls0[1]);
        float e00 = __expf(cls0[0] - m0), e01 = __expf(cls0[1] - m0);
        float i0 = 1.f / (e00 + e01);
        out[b0 * NK + 0] = e00 * i0;
        out[b0 * NK + 1] = e01 * i0;

        float m1 = fmaxf(cls1[0], cls1[1]);
        float e10 = __expf(cls1[0] - m1), e11 = __expf(cls1[1] - m1);
        float i1 = 1.f / (e10 + e11);
        out[b1 * NK + 0] = e10 * i1;
        out[b1 * NK + 1] = e11 * i1;
    }
}

extern "C" void kernel_launch(void* const* d_in, const int* in_sizes, int n_in,
                              void* d_out, int out_size) {
    const float* u = (const float*)d_in[0];   // [1024, 2336, 4]
    const float* W = (const float*)d_in[1];   // [2, 2336, 4, 16]
    float* out = (float*)d_out;               // [1024, 2]

    const int wtotal = NK * 16 * RR;
    wtrans_kernel<<<(wtotal + 255) / 256, 256>>>(W);

    const int smem_bytes = (RR * 16 + NWARP * 4 * 8 + 16) * sizeof(float);
    cudaFuncSetAttribute(caps_kernel,
                         cudaFuncAttributeMaxDynamicSharedMemorySize, smem_bytes);
    caps_kernel<<<512, NTHREADS, smem_bytes>>>(u, out);
}

// round 7
// speedup vs baseline: 2.0169x; 2.0169x over previous
#include <cuda_runtime.h>
#include <math.h>

#define RR       2336
#define CIN      4
#define COUT     16
#define NK       2
#define NTHREADS 512
#define NWARP    16
#define RPTF     4            // full j iterations (4*512 = 2048)
#define RPT      5
#define TAILN    288          // 2336 - 2048 (= 9 full warps -> warp-uniform tail)
#define RPAD     20           // floats per smem row (conflict-free float4 slots)

// W repacked: [k][og][i][r] float4 (float4 covers outputs o = og*4 .. og*4+3)
__device__ float4 g_Wt4[NK * 16 * RR];

__global__ void wtrans_kernel(const float* __restrict__ W) {
    int t = blockIdx.x * blockDim.x + threadIdx.x;
    if (t >= NK * 16 * RR) return;
    int r  = t % RR;
    int q  = t / RR;          // k*16 + og*4 + i
    int i  = q & 3;
    int og = (q >> 2) & 3;
    int k  = q >> 4;
    const float4* src = (const float4*)W;   // [(k,r,i)][og]
    g_Wt4[t] = src[((k * RR + r) * CIN + i) * 4 + og];
}

// two-stage block reduction: intra-warp shfl, then warp 0 combines (N <= 32)
template <int N>
__device__ __forceinline__ void block_sum(float* v, float* red, int lane, int wid) {
#pragma unroll
    for (int n = 0; n < N; ++n) {
        float x = v[n];
#pragma unroll
        for (int off = 16; off > 0; off >>= 1)
            x += __shfl_xor_sync(0xffffffffu, x, off);
        v[n] = x;
    }
    __syncthreads();          // previous users of red are done
    if (lane == 0) {
#pragma unroll
        for (int n = 0; n < N; ++n) red[wid * N + n] = v[n];
    }
    __syncthreads();
    if (wid == 0 && lane < N) {
        float t = red[lane];
#pragma unroll
        for (int w = 1; w < NWARP; ++w) t += red[w * N + lane];
        red[lane] = t;        // each lane owns its column; safe overwrite
    }
    __syncthreads();
#pragma unroll
    for (int n = 0; n < N; ++n) v[n] = red[n];   // broadcast reads
}

__device__ __forceinline__ void squash16(const float* s, float* v) {
    float n0 = 0.f, n1 = 0.f;
#pragma unroll
    for (int o = 0; o < 8; ++o) {
        n0 = fmaf(s[o], s[o], n0);
        n1 = fmaf(s[o + 8], s[o + 8], n1);
    }
    float n = n0 + n1;
    float f = sqrtf(n) / (1.f + n);
#pragma unroll
    for (int o = 0; o < COUT; ++o) v[o] = s[o] * f;
}

__device__ __forceinline__ float dot16(const float* a, const float* b) {
    float d0 = 0.f, d1 = 0.f, d2 = 0.f, d3 = 0.f;
#pragma unroll
    for (int o = 0; o < 4; ++o) {
        d0 = fmaf(a[o],      b[o],      d0);
        d1 = fmaf(a[o + 4],  b[o + 4],  d1);
        d2 = fmaf(a[o + 8],  b[o + 8],  d2);
        d3 = fmaf(a[o + 12], b[o + 12], d3);
    }
    return (d0 + d1) + (d2 + d3);
}

// one block = one batch; u_ji lives entirely in smem (thread-private rows)
__global__ __launch_bounds__(NTHREADS, 1)
void caps_kernel(const float* __restrict__ u, float* __restrict__ out) {
    extern __shared__ float sm[];
    float4* uji4 = (float4*)sm;         // route r, group og at slot r*5+og
    float*  red  = sm + RR * RPAD;

    const int tid  = threadIdx.x;
    const int lane = tid & 31;
    const int wid  = tid >> 5;
    const int b    = blockIdx.x;
    const float4* up = (const float4*)(u + (size_t)b * RR * CIN);
    const bool tailok = (tid < TAILN);  // warp-uniform

    float cls[NK];

    for (int k = 0; k < NK; ++k) {
        const float4* Wt4 = g_Wt4 + k * 16 * RR;

        // ===== Phase A: u_ji -> smem, init route-sum folded into same pass =====
        float ss[COUT];
#pragma unroll
        for (int o = 0; o < COUT; ++o) ss[o] = 0.f;

#define ROUTE_A(RVAL)                                                          \
        {                                                                      \
            const int r_ = (RVAL);                                             \
            float4 a = up[r_];                                                 \
            _Pragma("unroll")                                                  \
            for (int og = 0; og < 4; ++og) {                                   \
                float4 w0 = Wt4[(og * 4 + 0) * RR + r_];                       \
                float4 w1 = Wt4[(og * 4 + 1) * RR + r_];                       \
                float4 w2 = Wt4[(og * 4 + 2) * RR + r_];                       \
                float4 w3 = Wt4[(og * 4 + 3) * RR + r_];                       \
                float e0 = fmaf(a.x,w0.x, fmaf(a.y,w1.x, fmaf(a.z,w2.x, a.w*w3.x))); \
                float e1 = fmaf(a.x,w0.y, fmaf(a.y,w1.y, fmaf(a.z,w2.y, a.w*w3.y))); \
                float e2 = fmaf(a.x,w0.z, fmaf(a.y,w1.z, fmaf(a.z,w2.z, a.w*w3.z))); \
                float e3 = fmaf(a.x,w0.w, fmaf(a.y,w1.w, fmaf(a.z,w2.w, a.w*w3.w))); \
                uji4[r_ * 5 + og] = make_float4(e0, e1, e2, e3);               \
                ss[og * 4 + 0] += e0; ss[og * 4 + 1] += e1;                    \
                ss[og * 4 + 2] += e2; ss[og * 4 + 3] += e3;                    \
            }                                                                  \
        }

#pragma unroll
        for (int j = 0; j < RPTF; ++j)
            ROUTE_A(tid + j * NTHREADS)
        if (tailok)
            ROUTE_A(tid + RPTF * NTHREADS)

        // ===== init reduction + squash =====
        float v[COUT];
        block_sum<COUT>(ss, red, lane, wid);
#pragma unroll
        for (int o = 0; o < COUT; ++o) ss[o] *= (1.f / RR);
        squash16(ss, v);

        // ===== 2 fused routing iterations (single sweep each) =====
        float blr[RPT];
#pragma unroll
        for (int it = 0; it < 2; ++it) {
            float acc[COUT + 1];
#pragma unroll
            for (int o = 0; o <= COUT; ++o) acc[o] = 0.f;

#define SWEEP(JIDX, RVAL)                                                      \
            {                                                                  \
                const int r_ = (RVAL);                                         \
                float4 q0 = uji4[r_ * 5 + 0];                                  \
                float4 q1 = uji4[r_ * 5 + 1];                                  \
                float4 q2 = uji4[r_ * 5 + 2];                                  \
                float4 q3 = uji4[r_ * 5 + 3];                                  \
                float qq[COUT] = {q0.x,q0.y,q0.z,q0.w, q1.x,q1.y,q1.z,q1.w,    \
                                  q2.x,q2.y,q2.z,q2.w, q3.x,q3.y,q3.z,q3.w};   \
                float d  = dot16(qq, v);                                       \
                float nb = (it == 0) ? d : (blr[JIDX] + d);                    \
                blr[JIDX] = nb;                                                \
                float w = __expf(nb);                                          \
                acc[COUT] += w;                                                \
                _Pragma("unroll")                                              \
                for (int o = 0; o < COUT; ++o)                                 \
                    acc[o] = fmaf(w, qq[o], acc[o]);                           \
            }

#pragma unroll
            for (int j = 0; j < RPTF; ++j)
                SWEEP(j, tid + j * NTHREADS)
            if (tailok)
                SWEEP(RPTF, tid + RPTF * NTHREADS)

            block_sum<COUT + 1>(acc, red, lane, wid);
            float invZ = 1.f / acc[COUT];
            float s[COUT];
#pragma unroll
            for (int o = 0; o < COUT; ++o) s[o] = acc[o] * invZ;
            squash16(s, v);
        }
        cls[k] = sqrtf(dot16(v, v));
        // uji4 rows are thread-private; block_sum barriers order the k loop
    }

    // ===== final 2-way softmax =====
    if (tid == 0) {
        float m = fmaxf(cls[0], cls[1]);
        float e0 = __expf(cls[0] - m), e1 = __expf(cls[1] - m);
        float inv = 1.f / (e0 + e1);
        out[b * NK + 0] = e0 * inv;
        out[b * NK + 1] = e1 * inv;
    }
}

extern "C" void kernel_launch(void* const* d_in, const int* in_sizes, int n_in,
                              void* d_out, int out_size) {
    const float* u = (const float*)d_in[0];   // [1024, 2336, 4]
    const float* W = (const float*)d_in[1];   // [2, 2336, 4, 16]
    float* out = (float*)d_out;               // [1024, 2]

    const int wtotal = NK * 16 * RR;
    wtrans_kernel<<<(wtotal + 255) / 256, 256>>>(W);

    const int smem_bytes = (RR * RPAD + NWARP * 17 + 16) * sizeof(float);
    cudaFuncSetAttribute(caps_kernel,
                         cudaFuncAttributeMaxDynamicSharedMemorySize, smem_bytes);
    caps_kernel<<<1024, NTHREADS, smem_bytes>>>(u, out);
}